// round 14
// baseline (speedup 1.0000x reference)
#include <cuda_runtime.h>
#include <cuda_fp16.h>
#include <cuda_fp8.h>
#include <math.h>
#include <cstdint>

#define N_ROWS 8192
#define DIM    512
#define MARGIN 0.5f

#define TILE   128
#define KC     128                     // K chunk (fp8 elems) = 128 bytes/row
#define NCHUNK (DIM / KC)              // 4
#define NTILES (N_ROWS / TILE)         // 64
#define NBLOCKS (NTILES * (NTILES + 1) / 2)   // 2080

#define PITCH  (KC + 16)               // 144 B row pitch, ldmatrix conflict-free

// Scratch: normalized embeddings in e4m3
__device__ uint8_t g_E8[(size_t)N_ROWS * DIM];
__device__ double g_sum;
__device__ unsigned int g_done = 0;

// ---------------------------------------------------------------------------
__device__ __forceinline__ uint32_t smem_u32(const void* p) {
    uint32_t a;
    asm("{ .reg .u64 t; cvta.to.shared.u64 t, %1; cvt.u32.u64 %0, t; }"
        : "=r"(a) : "l"(p));
    return a;
}
__device__ __forceinline__ void ldmx4(uint32_t* r, uint32_t addr) {
    asm volatile("ldmatrix.sync.aligned.m8n8.x4.shared.b16 {%0,%1,%2,%3}, [%4];"
                 : "=r"(r[0]), "=r"(r[1]), "=r"(r[2]), "=r"(r[3]) : "r"(addr));
}
// FP8 e4m3 MMA, f32 accumulate: m16n8k32
__device__ __forceinline__ void mma_fp8(float* d, const uint32_t* a,
                                        uint32_t b0, uint32_t b1) {
    asm volatile(
        "mma.sync.aligned.m16n8k32.row.col.f32.e4m3.e4m3.f32 "
        "{%0,%1,%2,%3}, {%4,%5,%6,%7}, {%8,%9}, {%0,%1,%2,%3};"
        : "+f"(d[0]), "+f"(d[1]), "+f"(d[2]), "+f"(d[3])
        : "r"(a[0]), "r"(a[1]), "r"(a[2]), "r"(a[3]), "r"(b0), "r"(b1));
}
__device__ __forceinline__ void cp_async16(uint32_t smem_dst, const void* gmem_src) {
    asm volatile("cp.async.cg.shared.global [%0], [%1], 16;"
                 :: "r"(smem_dst), "l"(gmem_src) : "memory");
}
__device__ __forceinline__ void cp_commit() {
    asm volatile("cp.async.commit_group;" ::: "memory");
}
template <int N>
__device__ __forceinline__ void cp_wait() {
    asm volatile("cp.async.wait_group %0;" :: "n"(N) : "memory");
}

// ---------------------------------------------------------------------------
// Kernel 1: normalize + e4m3 convert. Warp per row, 8 rows/block.
// ---------------------------------------------------------------------------
__global__ void normalize_kernel(const float* __restrict__ emb) {
    const int wid  = threadIdx.x >> 5;
    const int lane = threadIdx.x & 31;
    const int row  = blockIdx.x * 8 + wid;
    if (row == 0 && lane == 0) g_sum = 0.0;   // stream-ordered before loss_kernel

    const float4* src = reinterpret_cast<const float4*>(emb + (size_t)row * DIM);
    float4 v[4];
    float ss = 0.0f;
#pragma unroll
    for (int k = 0; k < 4; k++) {
        v[k] = src[lane + 32 * k];
        ss += v[k].x*v[k].x + v[k].y*v[k].y + v[k].z*v[k].z + v[k].w*v[k].w;
    }
    for (int off = 16; off > 0; off >>= 1)
        ss += __shfl_xor_sync(0xFFFFFFFF, ss, off);
    const float sc = 1.0f / fmaxf(sqrtf(ss), 1e-12f);

    uint32_t w[4];
#pragma unroll
    for (int k = 0; k < 4; k++) {
        __nv_fp8x2_storage_t lo = __nv_cvt_float2_to_fp8x2(
            make_float2(v[k].x * sc, v[k].y * sc), __NV_SATFINITE, __NV_E4M3);
        __nv_fp8x2_storage_t hi = __nv_cvt_float2_to_fp8x2(
            make_float2(v[k].z * sc, v[k].w * sc), __NV_SATFINITE, __NV_E4M3);
        w[k] = (uint32_t)lo | ((uint32_t)hi << 16);
    }
    uint4 o; o.x = w[0]; o.y = w[1]; o.z = w[2]; o.w = w[3];
    reinterpret_cast<uint4*>(g_E8 + (size_t)row * DIM)[lane] = o;
}

// ---------------------------------------------------------------------------
// Kernel 2: fp8 e4m3 sim-GEMM (f32 acc), upper triangle, fused loss+finalize.
// 128x128 CTA tile, 4 warps (2x2), warp tile 64x64.
// cp.async double buffer (smem) + fragment double buffer (regs).
// ---------------------------------------------------------------------------
#define SM_RLAB 0
#define SM_CLAB 512
#define SM_RED  1024
#define SM_BUF  1088
#define BUFSZ   (2 * TILE * PITCH)     // A+B per stage: 36864 B
#define SM_TOT  (SM_BUF + 2 * BUFSZ)   // 74816 B

__global__ __launch_bounds__(128, 2) void loss_kernel(const int* __restrict__ labels,
                                                      float* __restrict__ out) {
    extern __shared__ char smem[];
    const uint32_t sbase = smem_u32(smem);
    const int tid  = threadIdx.x;      // 0..127
    const int wid  = tid >> 5;         // 0..3
    const int lane = tid & 31;
    const int wr   = wid >> 1;    // 0..1 : 64-row band
    const int wc   = wid & 1;     // 0..1 : 64-col band

    // Triangular decode blockIdx.x -> (bi, bj), bj >= bi
    int idx = blockIdx.x;
    int bi = (int)((2.0f * NTILES + 1.0f
                    - sqrtf((2.0f*NTILES+1.0f)*(2.0f*NTILES+1.0f) - 8.0f*idx)) * 0.5f);
    while (bi > 0 && bi * NTILES - (bi * (bi - 1)) / 2 > idx) bi--;
    while ((bi + 1) * NTILES - ((bi + 1) * bi) / 2 <= idx) bi++;
    const int bj = bi + (idx - (bi * NTILES - (bi * (bi - 1)) / 2));

    const int rowBase = bi * TILE;
    const int colBase = bj * TILE;

    int* sRlab = reinterpret_cast<int*>(smem + SM_RLAB);
    int* sClab = reinterpret_cast<int*>(smem + SM_CLAB);
    sRlab[tid] = labels[rowBase + tid];
    sClab[tid] = labels[colBase + tid];

    // cp.async mapping: 16 x 16B per thread per chunk
    int cp_row[16]; int cp_isB[16]; int cp_g[16];
#pragma unroll
    for (int p = 0; p < 16; p++) {
        const int e = tid + p * 128;
        cp_isB[p] = e >> 10;
        cp_row[p] = (e & 1023) >> 3;
        cp_g[p]   = e & 7;
    }

    // ldmatrix per-lane bases (relative to buffer start)
    const int lrow = lane & 15;
    const uint32_t khalf = (lane & 16) ? 16u : 0u;
    const uint32_t aRel = (uint32_t)(wr * 64 + lrow) * PITCH + khalf;
    const uint32_t bRel = (uint32_t)(TILE * PITCH) + (uint32_t)(wc * 64 + lrow) * PITCH + khalf;

    float acc[4][8][4];
#pragma unroll
    for (int i = 0; i < 4; i++)
#pragma unroll
        for (int j = 0; j < 8; j++)
#pragma unroll
            for (int q = 0; q < 4; q++) acc[i][j][q] = 0.0f;

    // ---- prefetch chunk 0 into smem buffer 0 ----
#pragma unroll
    for (int p = 0; p < 16; p++) {
        const int gro = (cp_isB[p] ? colBase : rowBase) + cp_row[p];
        const uint32_t dst = sbase + SM_BUF
            + (uint32_t)(cp_isB[p] * (TILE * PITCH) + cp_row[p] * PITCH + cp_g[p] * 16);
        cp_async16(dst, g_E8 + (size_t)gro * DIM + cp_g[p] * 16);
    }
    cp_commit();

    // register fragment double buffers
    uint32_t afr[2][4][4];
    uint32_t bfr[2][4][4];

#pragma unroll 1
    for (int c = 0; c < NCHUNK; c++) {
        const uint32_t curBuf = sbase + SM_BUF + (uint32_t)((c & 1) * BUFSZ);

        if (c + 1 < NCHUNK) {
            const uint32_t nxtBuf = sbase + SM_BUF + (uint32_t)(((c + 1) & 1) * BUFSZ);
            const int koff = (c + 1) * KC;
#pragma unroll
            for (int p = 0; p < 16; p++) {
                const int gro = (cp_isB[p] ? colBase : rowBase) + cp_row[p];
                const uint32_t dst = nxtBuf
                    + (uint32_t)(cp_isB[p] * (TILE * PITCH) + cp_row[p] * PITCH + cp_g[p] * 16);
                cp_async16(dst, g_E8 + (size_t)gro * DIM + koff + cp_g[p] * 16);
            }
            cp_commit();
            cp_wait<1>();
        } else {
            cp_wait<0>();
        }
        __syncthreads();

        const uint32_t aAddr = curBuf + aRel;
        const uint32_t bAddr = curBuf + bRel;

        // preload ks=0 fragments
#pragma unroll
        for (int mi = 0; mi < 4; mi++)
            ldmx4(afr[0][mi], aAddr + (uint32_t)(mi * 16) * PITCH);
#pragma unroll
        for (int nb = 0; nb < 4; nb++)
            ldmx4(bfr[0][nb], bAddr + (uint32_t)(nb * 16) * PITCH);

        // 4 k-steps of k32; load ks+1 fragments while issuing ks QMMAs
#pragma unroll
        for (int ks = 0; ks < KC / 32; ks++) {
            const int cur = ks & 1;
            if (ks + 1 < KC / 32) {
                const uint32_t ko = (ks + 1) * 32;
#pragma unroll
                for (int mi = 0; mi < 4; mi++)
                    ldmx4(afr[cur ^ 1][mi], aAddr + (uint32_t)(mi * 16) * PITCH + ko);
#pragma unroll
                for (int nb = 0; nb < 4; nb++)
                    ldmx4(bfr[cur ^ 1][nb], bAddr + (uint32_t)(nb * 16) * PITCH + ko);
            }
#pragma unroll
            for (int mi = 0; mi < 4; mi++) {
#pragma unroll
                for (int ni = 0; ni < 8; ni++) {
                    const uint32_t b0 = bfr[cur][ni >> 1][ni & 1];
                    const uint32_t b1 = bfr[cur][ni >> 1][2 + (ni & 1)];
                    mma_fp8(acc[mi][ni], afr[cur][mi], b0, b1);
                }
            }
        }
        __syncthreads();
    }

    // ---- fused loss epilogue (branch-free) ----
    float local = 0.0f;
#pragma unroll
    for (int mi = 0; mi < 4; mi++) {
        const int r0 = wr * 64 + mi * 16 + (lane >> 2);
#pragma unroll
        for (int ni = 0; ni < 8; ni++) {
            const int c0 = wc * 64 + ni * 8 + ((lane & 3) << 1);
#pragma unroll
            for (int h = 0; h < 2; h++) {
                const int ri = r0 + h * 8;
                const int gi = rowBase + ri;
                const int la = sRlab[ri];
#pragma unroll
                for (int q = 0; q < 2; q++) {
                    const int cj = c0 + q;
                    const int gj = colBase + cj;
                    const float s = acc[mi][ni][h * 2 + q];
                    const float e1 = 1.0f - s;
                    const float e2 = fmaxf(s - MARGIN, 0.0f);
                    float t = (la == sClab[cj]) ? e1 : e2;
                    t = (gi == gj) ? 0.0f : t;
                    local = fmaf(t, t, local);
                }
            }
        }
    }
    if (bi != bj) local *= 2.0f;   // symmetric tile counted twice

    // reduce: warp -> block -> global; last CTA finalizes
    for (int off = 16; off > 0; off >>= 1)
        local += __shfl_xor_sync(0xFFFFFFFF, local, off);
    float* sRed = reinterpret_cast<float*>(smem + SM_RED);
    if (lane == 0) sRed[wid] = local;
    __syncthreads();
    if (tid == 0) {
        const float t = sRed[0] + sRed[1] + sRed[2] + sRed[3];
        atomicAdd(&g_sum, (double)t);
        __threadfence();
        const unsigned int r = atomicAdd(&g_done, 1u);
        if (r == NBLOCKS - 1) {
            const double num_pairs = (double)N_ROWS * (double)(N_ROWS - 1);
            out[0] = (float)(g_sum / num_pairs);
            g_done = 0;   // reset for next replay (deterministic)
        }
    }
}

// ---------------------------------------------------------------------------
extern "C" void kernel_launch(void* const* d_in, const int* in_sizes, int n_in,
                              void* d_out, int out_size) {
    const float* embeddings = (const float*)d_in[0];
    const int*   labels     = (const int*)d_in[1];
    float*       out        = (float*)d_out;

    static bool attr_set = false;
    if (!attr_set) {
        cudaFuncSetAttribute(loss_kernel,
                             cudaFuncAttributeMaxDynamicSharedMemorySize, SM_TOT);
        attr_set = true;
    }

    normalize_kernel<<<N_ROWS / 8, 256>>>(embeddings);
    loss_kernel<<<NBLOCKS, 128, SM_TOT>>>(labels, out);
}

// round 15
// speedup vs baseline: 1.1575x; 1.1575x over previous
#include <cuda_runtime.h>
#include <cuda_fp16.h>
#include <math.h>
#include <cstdint>

#define N_ROWS 8192
#define DIM    512
#define MARGIN 0.5f

#define TILE   128
#define KC     64                      // K chunk (fp16 elems) = 128 B/row
#define NCHUNK (DIM / KC)              // 8
#define NTILES (N_ROWS / TILE)         // 64
#define NBLOCKS (NTILES * (NTILES + 1) / 2)   // 2080

#define PITCH  (KC * 2 + 16)           // 144 B row pitch, ldmatrix conflict-free

// Scratch: normalized embeddings in fp16
__device__ __half g_Ehf[(size_t)N_ROWS * DIM];
__device__ double g_sum;
__device__ unsigned int g_done = 0;

// ---------------------------------------------------------------------------
__device__ __forceinline__ uint32_t smem_u32(const void* p) {
    uint32_t a;
    asm("{ .reg .u64 t; cvta.to.shared.u64 t, %1; cvt.u32.u64 %0, t; }"
        : "=r"(a) : "l"(p));
    return a;
}
__device__ __forceinline__ void ldmx4(uint32_t* r, uint32_t addr) {
    asm volatile("ldmatrix.sync.aligned.m8n8.x4.shared.b16 {%0,%1,%2,%3}, [%4];"
                 : "=r"(r[0]), "=r"(r[1]), "=r"(r[2]), "=r"(r[3]) : "r"(addr));
}
// f16-accumulate MMA
__device__ __forceinline__ void mma16816_f16(uint32_t* d, const uint32_t* a,
                                             uint32_t b0, uint32_t b1) {
    asm volatile(
        "mma.sync.aligned.m16n8k16.row.col.f16.f16.f16.f16 "
        "{%0,%1}, {%2,%3,%4,%5}, {%6,%7}, {%0,%1};"
        : "+r"(d[0]), "+r"(d[1])
        : "r"(a[0]), "r"(a[1]), "r"(a[2]), "r"(a[3]), "r"(b0), "r"(b1));
}
__device__ __forceinline__ void cp_async16(uint32_t smem_dst, const void* gmem_src) {
    asm volatile("cp.async.cg.shared.global [%0], [%1], 16;"
                 :: "r"(smem_dst), "l"(gmem_src) : "memory");
}
__device__ __forceinline__ void cp_commit() {
    asm volatile("cp.async.commit_group;" ::: "memory");
}
template <int N>
__device__ __forceinline__ void cp_wait() {
    asm volatile("cp.async.wait_group %0;" :: "n"(N) : "memory");
}

// ---------------------------------------------------------------------------
// Kernel 1: normalize + fp16 convert. Warp per row, 8 rows/block.
// ---------------------------------------------------------------------------
__global__ void normalize_kernel(const float* __restrict__ emb) {
    const int wid  = threadIdx.x >> 5;
    const int lane = threadIdx.x & 31;
    const int row  = blockIdx.x * 8 + wid;
    if (row == 0 && lane == 0) g_sum = 0.0;   // stream-ordered before loss_kernel

    const float4* src = reinterpret_cast<const float4*>(emb + (size_t)row * DIM);
    float4 v[4];
    float ss = 0.0f;
#pragma unroll
    for (int k = 0; k < 4; k++) {
        v[k] = src[lane + 32 * k];
        ss += v[k].x*v[k].x + v[k].y*v[k].y + v[k].z*v[k].z + v[k].w*v[k].w;
    }
    for (int off = 16; off > 0; off >>= 1)
        ss += __shfl_xor_sync(0xFFFFFFFF, ss, off);
    const float sc = 1.0f / fmaxf(sqrtf(ss), 1e-12f);

    uint2* dst = reinterpret_cast<uint2*>(g_Ehf + (size_t)row * DIM);
#pragma unroll
    for (int k = 0; k < 4; k++) {
        __half2 p0 = __floats2half2_rn(v[k].x * sc, v[k].y * sc);
        __half2 p1 = __floats2half2_rn(v[k].z * sc, v[k].w * sc);
        uint2 o;
        o.x = *reinterpret_cast<uint32_t*>(&p0);
        o.y = *reinterpret_cast<uint32_t*>(&p1);
        dst[lane + 32 * k] = o;
    }
}

// ---------------------------------------------------------------------------
// Kernel 2: fp16 (f16-acc) sim-GEMM, upper triangle, fused loss+finalize.
// 128x128 CTA tile, 4 warps (2x2), warp tile 64x64.
// cp.async smem double buffer + register fragment double buffer.
// ---------------------------------------------------------------------------
#define SM_RLAB 0
#define SM_CLAB 512
#define SM_RED  1024
#define SM_BUF  1088
#define BUFSZ   (2 * TILE * PITCH)     // A+B per stage: 36864 B
#define SM_TOT  (SM_BUF + 2 * BUFSZ)   // 74816 B

__global__ __launch_bounds__(128, 2) void loss_kernel(const int* __restrict__ labels,
                                                      float* __restrict__ out) {
    extern __shared__ char smem[];
    const uint32_t sbase = smem_u32(smem);
    const int tid  = threadIdx.x;      // 0..127
    const int wid  = tid >> 5;         // 0..3
    const int lane = tid & 31;
    const int wr   = wid >> 1;    // 0..1 : 64-row band
    const int wc   = wid & 1;     // 0..1 : 64-col band

    // Triangular decode blockIdx.x -> (bi, bj), bj >= bi
    int idx = blockIdx.x;
    int bi = (int)((2.0f * NTILES + 1.0f
                    - sqrtf((2.0f*NTILES+1.0f)*(2.0f*NTILES+1.0f) - 8.0f*idx)) * 0.5f);
    while (bi > 0 && bi * NTILES - (bi * (bi - 1)) / 2 > idx) bi--;
    while ((bi + 1) * NTILES - ((bi + 1) * bi) / 2 <= idx) bi++;
    const int bj = bi + (idx - (bi * NTILES - (bi * (bi - 1)) / 2));

    const int rowBase = bi * TILE;
    const int colBase = bj * TILE;

    int* sRlab = reinterpret_cast<int*>(smem + SM_RLAB);
    int* sClab = reinterpret_cast<int*>(smem + SM_CLAB);
    sRlab[tid] = labels[rowBase + tid];
    sClab[tid] = labels[colBase + tid];

    // Closed-form cp.async mapping (128 threads, 16 transfers each):
    //   p in [0,16): isB = (p>=8), rloc = (tid>>3) + (p&7)*16, g = tid&7
    const int rloc0 = tid >> 3;
    const int g     = tid & 7;
    const uint32_t dRel  = (uint32_t)(rloc0 * PITCH + g * 16);   // within A or B block
    const __half* srcA0 = g_Ehf + (size_t)(rowBase + rloc0) * DIM + g * 8;
    const __half* srcB0 = g_Ehf + (size_t)(colBase + rloc0) * DIM + g * 8;

    // ldmatrix per-lane bases (relative to buffer start)
    const int lrow = lane & 15;
    const uint32_t khalf = (lane & 16) ? 16u : 0u;
    const uint32_t aRel = (uint32_t)(wr * 64 + lrow) * PITCH + khalf;
    const uint32_t bRel = (uint32_t)(TILE * PITCH) + (uint32_t)(wc * 64 + lrow) * PITCH + khalf;

    // f16 accumulators: [mi][ni] -> 2 packed regs
    uint32_t acc[4][8][2];
#pragma unroll
    for (int i = 0; i < 4; i++)
#pragma unroll
        for (int j = 0; j < 8; j++) { acc[i][j][0] = 0u; acc[i][j][1] = 0u; }

    // ---- prefetch chunk 0 into smem buffer 0 ----
    {
        const uint32_t st = sbase + SM_BUF;
#pragma unroll
        for (int p = 0; p < 8; p++)
            cp_async16(st + dRel + (uint32_t)(p * 16 * PITCH),
                       srcA0 + (size_t)(p * 16) * DIM);
#pragma unroll
        for (int p = 0; p < 8; p++)
            cp_async16(st + (uint32_t)(TILE * PITCH) + dRel + (uint32_t)(p * 16 * PITCH),
                       srcB0 + (size_t)(p * 16) * DIM);
        cp_commit();
    }

    // register fragment double buffers (32 + 32 regs)
    uint32_t afr[2][4][4];
    uint32_t bfr[2][4][4];

#pragma unroll 1
    for (int c = 0; c < NCHUNK; c++) {
        const uint32_t curBuf = sbase + SM_BUF + (uint32_t)((c & 1) * BUFSZ);

        if (c + 1 < NCHUNK) {
            const uint32_t nxtBuf = sbase + SM_BUF + (uint32_t)(((c + 1) & 1) * BUFSZ);
            const int koff = (c + 1) * KC;
#pragma unroll
            for (int p = 0; p < 8; p++)
                cp_async16(nxtBuf + dRel + (uint32_t)(p * 16 * PITCH),
                           srcA0 + (size_t)(p * 16) * DIM + koff);
#pragma unroll
            for (int p = 0; p < 8; p++)
                cp_async16(nxtBuf + (uint32_t)(TILE * PITCH) + dRel + (uint32_t)(p * 16 * PITCH),
                           srcB0 + (size_t)(p * 16) * DIM + koff);
            cp_commit();
            cp_wait<1>();
        } else {
            cp_wait<0>();
        }
        __syncthreads();

        const uint32_t aAddr = curBuf + aRel;
        const uint32_t bAddr = curBuf + bRel;

        // preload ks=0 fragments
#pragma unroll
        for (int mi = 0; mi < 4; mi++)
            ldmx4(afr[0][mi], aAddr + (uint32_t)(mi * 16) * PITCH);
#pragma unroll
        for (int nb = 0; nb < 4; nb++)
            ldmx4(bfr[0][nb], bAddr + (uint32_t)(nb * 16) * PITCH);

        // 4 k-steps of k16; load ks+1 fragments while issuing ks MMAs
#pragma unroll
        for (int ks = 0; ks < KC / 16; ks++) {
            const int cur = ks & 1;
            if (ks + 1 < KC / 16) {
                const uint32_t ko = (ks + 1) * 32;  // bytes
#pragma unroll
                for (int mi = 0; mi < 4; mi++)
                    ldmx4(afr[cur ^ 1][mi], aAddr + (uint32_t)(mi * 16) * PITCH + ko);
#pragma unroll
                for (int nb = 0; nb < 4; nb++)
                    ldmx4(bfr[cur ^ 1][nb], bAddr + (uint32_t)(nb * 16) * PITCH + ko);
            }
#pragma unroll
            for (int mi = 0; mi < 4; mi++) {
#pragma unroll
                for (int ni = 0; ni < 8; ni++) {
                    const uint32_t b0 = bfr[cur][ni >> 1][ni & 1];
                    const uint32_t b1 = bfr[cur][ni >> 1][2 + (ni & 1)];
                    mma16816_f16(acc[mi][ni], afr[cur][mi], b0, b1);
                }
            }
        }
        __syncthreads();
    }

    // ---- fused loss epilogue (branch-free) ----
    float local = 0.0f;
#pragma unroll
    for (int mi = 0; mi < 4; mi++) {
        const int r0 = wr * 64 + mi * 16 + (lane >> 2);
#pragma unroll
        for (int ni = 0; ni < 8; ni++) {
            const int c0 = wc * 64 + ni * 8 + ((lane & 3) << 1);
#pragma unroll
            for (int h = 0; h < 2; h++) {
                const int ri = r0 + h * 8;
                const int gi = rowBase + ri;
                const int la = sRlab[ri];
                const __half2 hv = *reinterpret_cast<const __half2*>(&acc[mi][ni][h]);
                const float2 sv = __half22float2(hv);
#pragma unroll
                for (int q = 0; q < 2; q++) {
                    const int cj = c0 + q;
                    const int gj = colBase + cj;
                    const float s = (q == 0) ? sv.x : sv.y;
                    const float e1 = 1.0f - s;
                    const float e2 = fmaxf(s - MARGIN, 0.0f);
                    float t = (la == sClab[cj]) ? e1 : e2;
                    t = (gi == gj) ? 0.0f : t;
                    local = fmaf(t, t, local);
                }
            }
        }
    }
    if (bi != bj) local *= 2.0f;   // symmetric tile counted twice

    // reduce: warp -> block -> global; last CTA finalizes
    for (int off = 16; off > 0; off >>= 1)
        local += __shfl_xor_sync(0xFFFFFFFF, local, off);
    float* sRed = reinterpret_cast<float*>(smem + SM_RED);
    if (lane == 0) sRed[wid] = local;
    __syncthreads();
    if (tid == 0) {
        const float t = sRed[0] + sRed[1] + sRed[2] + sRed[3];
        atomicAdd(&g_sum, (double)t);
        __threadfence();
        const unsigned int r = atomicAdd(&g_done, 1u);
        if (r == NBLOCKS - 1) {
            const double num_pairs = (double)N_ROWS * (double)(N_ROWS - 1);
            out[0] = (float)(g_sum / num_pairs);
            g_done = 0;   // reset for next replay (deterministic)
        }
    }
}

// ---------------------------------------------------------------------------
extern "C" void kernel_launch(void* const* d_in, const int* in_sizes, int n_in,
                              void* d_out, int out_size) {
    const float* embeddings = (const float*)d_in[0];
    const int*   labels     = (const int*)d_in[1];
    float*       out        = (float*)d_out;

    static bool attr_set = false;
    if (!attr_set) {
        cudaFuncSetAttribute(loss_kernel,
                             cudaFuncAttributeMaxDynamicSharedMemorySize, SM_TOT);
        attr_set = true;
    }

    normalize_kernel<<<N_ROWS / 8, 256>>>(embeddings);
    loss_kernel<<<NBLOCKS, 128, SM_TOT>>>(labels, out);
}

// round 16
// speedup vs baseline: 1.8165x; 1.5694x over previous
#include <cuda_runtime.h>
#include <cuda_fp16.h>
#include <math.h>
#include <cstdint>

#define N_ROWS 8192
#define DIM    512
#define MARGIN 0.5f

#define TILE   128
#define KC     64                      // K chunk (fp16 elems)
#define NCHUNK (DIM / KC)              // 8
#define NTILES (N_ROWS / TILE)         // 64
#define NBLOCKS (NTILES * (NTILES + 1) / 2)   // 2080

#define PITCH  (KC * 2 + 16)           // 144 B row pitch, ldmatrix conflict-free

// Scratch: normalized embeddings in fp16
__device__ __half g_Ehf[(size_t)N_ROWS * DIM];
__device__ double g_sum;
__device__ unsigned int g_done = 0;

// ---------------------------------------------------------------------------
__device__ __forceinline__ uint32_t smem_u32(const void* p) {
    uint32_t a;
    asm("{ .reg .u64 t; cvta.to.shared.u64 t, %1; cvt.u32.u64 %0, t; }"
        : "=r"(a) : "l"(p));
    return a;
}
__device__ __forceinline__ void ldmx4(uint32_t* r, uint32_t addr) {
    asm volatile("ldmatrix.sync.aligned.m8n8.x4.shared.b16 {%0,%1,%2,%3}, [%4];"
                 : "=r"(r[0]), "=r"(r[1]), "=r"(r[2]), "=r"(r[3]) : "r"(addr));
}
// f16-accumulate MMA
__device__ __forceinline__ void mma16816_f16(uint32_t* d, const uint32_t* a,
                                             uint32_t b0, uint32_t b1) {
    asm volatile(
        "mma.sync.aligned.m16n8k16.row.col.f16.f16.f16.f16 "
        "{%0,%1}, {%2,%3,%4,%5}, {%6,%7}, {%0,%1};"
        : "+r"(d[0]), "+r"(d[1])
        : "r"(a[0]), "r"(a[1]), "r"(a[2]), "r"(a[3]), "r"(b0), "r"(b1));
}
__device__ __forceinline__ void cp_async16(uint32_t smem_dst, const void* gmem_src) {
    asm volatile("cp.async.cg.shared.global [%0], [%1], 16;"
                 :: "r"(smem_dst), "l"(gmem_src) : "memory");
}
__device__ __forceinline__ void cp_commit() {
    asm volatile("cp.async.commit_group;" ::: "memory");
}
template <int N>
__device__ __forceinline__ void cp_wait() {
    asm volatile("cp.async.wait_group %0;" :: "n"(N) : "memory");
}

// ---------------------------------------------------------------------------
// Kernel 1: normalize + fp16 convert. Warp per row, 8 rows/block.
// ---------------------------------------------------------------------------
__global__ void normalize_kernel(const float* __restrict__ emb) {
    const int wid  = threadIdx.x >> 5;
    const int lane = threadIdx.x & 31;
    const int row  = blockIdx.x * 8 + wid;
    if (row == 0 && lane == 0) g_sum = 0.0;   // stream-ordered before loss_kernel

    const float4* src = reinterpret_cast<const float4*>(emb + (size_t)row * DIM);
    float4 v[4];
    float ss = 0.0f;
#pragma unroll
    for (int k = 0; k < 4; k++) {
        v[k] = src[lane + 32 * k];
        ss += v[k].x*v[k].x + v[k].y*v[k].y + v[k].z*v[k].z + v[k].w*v[k].w;
    }
    for (int off = 16; off > 0; off >>= 1)
        ss += __shfl_xor_sync(0xFFFFFFFF, ss, off);
    const float sc = 1.0f / fmaxf(sqrtf(ss), 1e-12f);

    uint2* dst = reinterpret_cast<uint2*>(g_Ehf + (size_t)row * DIM);
#pragma unroll
    for (int k = 0; k < 4; k++) {
        __half2 p0 = __floats2half2_rn(v[k].x * sc, v[k].y * sc);
        __half2 p1 = __floats2half2_rn(v[k].z * sc, v[k].w * sc);
        uint2 o;
        o.x = *reinterpret_cast<uint32_t*>(&p0);
        o.y = *reinterpret_cast<uint32_t*>(&p1);
        dst[lane + 32 * k] = o;
    }
}

// ---------------------------------------------------------------------------
// Kernel 2: fp16 (f16-acc) sim-GEMM, upper triangle, fused loss + finalize.
// 128x128 CTA tile, 4 warps (2x2), warp tile 64x64, cp.async double buffer.
// (R10 mainloop — compiler-scheduled; manual pipelining regressed in R14/R15.)
// ---------------------------------------------------------------------------
#define SM_RLAB 0
#define SM_CLAB 512
#define SM_RED  1024
#define SM_BUF  1088
#define BUFSZ   (2 * TILE * PITCH)     // A+B per stage: 36864 B
#define SM_TOT  (SM_BUF + 2 * BUFSZ)   // 74816 B

__global__ __launch_bounds__(128, 2) void loss_kernel(const int* __restrict__ labels,
                                                      float* __restrict__ out) {
    extern __shared__ char smem[];
    const uint32_t sbase = smem_u32(smem);
    const int tid  = threadIdx.x;      // 0..127
    const int wid  = tid >> 5;         // 0..3
    const int lane = tid & 31;
    const int wr   = wid >> 1;    // 0..1 : 64-row band
    const int wc   = wid & 1;     // 0..1 : 64-col band

    // Triangular decode blockIdx.x -> (bi, bj), bj >= bi
    int idx = blockIdx.x;
    int bi = (int)((2.0f * NTILES + 1.0f
                    - sqrtf((2.0f*NTILES+1.0f)*(2.0f*NTILES+1.0f) - 8.0f*idx)) * 0.5f);
    while (bi > 0 && bi * NTILES - (bi * (bi - 1)) / 2 > idx) bi--;
    while ((bi + 1) * NTILES - ((bi + 1) * bi) / 2 <= idx) bi++;
    const int bj = bi + (idx - (bi * NTILES - (bi * (bi - 1)) / 2));

    const int rowBase = bi * TILE;
    const int colBase = bj * TILE;

    int* sRlab = reinterpret_cast<int*>(smem + SM_RLAB);
    int* sClab = reinterpret_cast<int*>(smem + SM_CLAB);
    sRlab[tid] = labels[rowBase + tid];
    sClab[tid] = labels[colBase + tid];

    // cp.async mapping: 16 x 16B per thread per chunk (2048 total)
    int cp_row[16]; int cp_isB[16]; int cp_g[16];
#pragma unroll
    for (int p = 0; p < 16; p++) {
        const int e = tid + p * 128;
        cp_isB[p] = e >> 10;
        cp_row[p] = (e & 1023) >> 3;
        cp_g[p]   = e & 7;
    }

    // ldmatrix per-lane bases (relative to buffer start)
    const int lrow = lane & 15;
    const uint32_t khalf = (lane & 16) ? 16u : 0u;
    const uint32_t aRel = (uint32_t)(wr * 64 + lrow) * PITCH + khalf;
    const uint32_t bRel = (uint32_t)(TILE * PITCH) + (uint32_t)(wc * 64 + lrow) * PITCH + khalf;

    // f16 accumulators: [mi][ni] -> 2 packed regs
    uint32_t acc[4][8][2];
#pragma unroll
    for (int i = 0; i < 4; i++)
#pragma unroll
        for (int j = 0; j < 8; j++) { acc[i][j][0] = 0u; acc[i][j][1] = 0u; }

    // ---- prefetch chunk 0 into buffer 0 ----
#pragma unroll
    for (int p = 0; p < 16; p++) {
        const int gro = (cp_isB[p] ? colBase : rowBase) + cp_row[p];
        const uint32_t dst = sbase + SM_BUF
            + (uint32_t)(cp_isB[p] * (TILE * PITCH) + cp_row[p] * PITCH + cp_g[p] * 16);
        cp_async16(dst, g_Ehf + (size_t)gro * DIM + cp_g[p] * 8);
    }
    cp_commit();

#pragma unroll 1
    for (int c = 0; c < NCHUNK; c++) {
        const uint32_t curBuf = sbase + SM_BUF + (uint32_t)((c & 1) * BUFSZ);

        if (c + 1 < NCHUNK) {
            const uint32_t nxtBuf = sbase + SM_BUF + (uint32_t)(((c + 1) & 1) * BUFSZ);
            const int koff = (c + 1) * KC;
#pragma unroll
            for (int p = 0; p < 16; p++) {
                const int gro = (cp_isB[p] ? colBase : rowBase) + cp_row[p];
                const uint32_t dst = nxtBuf
                    + (uint32_t)(cp_isB[p] * (TILE * PITCH) + cp_row[p] * PITCH + cp_g[p] * 16);
                cp_async16(dst, g_Ehf + (size_t)gro * DIM + koff + cp_g[p] * 8);
            }
            cp_commit();
            cp_wait<1>();
        } else {
            cp_wait<0>();
        }
        __syncthreads();

        const uint32_t aAddr = curBuf + aRel;
        const uint32_t bAddr = curBuf + bRel;
#pragma unroll
        for (int ks = 0; ks < KC / 16; ks++) {
            const uint32_t ko = ks * 32;  // bytes
            uint32_t a[4][4];
#pragma unroll
            for (int mi = 0; mi < 4; mi++)
                ldmx4(a[mi], aAddr + (uint32_t)(mi * 16) * PITCH + ko);
            uint32_t b[4][4];
#pragma unroll
            for (int nb = 0; nb < 4; nb++)
                ldmx4(b[nb], bAddr + (uint32_t)(nb * 16) * PITCH + ko);
#pragma unroll
            for (int mi = 0; mi < 4; mi++) {
#pragma unroll
                for (int ni = 0; ni < 8; ni++) {
                    const uint32_t b0 = b[ni >> 1][ni & 1];
                    const uint32_t b1 = b[ni >> 1][2 + (ni & 1)];
                    mma16816_f16(acc[mi][ni], a[mi], b0, b1);
                }
            }
        }
        __syncthreads();
    }

    // ---- fused loss epilogue on f16 register fragments ----
    float local = 0.0f;
#pragma unroll
    for (int mi = 0; mi < 4; mi++) {
        const int r0 = wr * 64 + mi * 16 + (lane >> 2);
#pragma unroll
        for (int ni = 0; ni < 8; ni++) {
            const int c0 = wc * 64 + ni * 8 + ((lane & 3) << 1);
#pragma unroll
            for (int h = 0; h < 2; h++) {
                const int ri = r0 + h * 8;
                const int gi = rowBase + ri;
                const int la = sRlab[ri];
                const __half2 hv = *reinterpret_cast<const __half2*>(&acc[mi][ni][h]);
                const float2 sv = __half22float2(hv);
#pragma unroll
                for (int q = 0; q < 2; q++) {
                    const int cj = c0 + q;
                    const int gj = colBase + cj;
                    if (gi == gj) continue;
                    const float s = (q == 0) ? sv.x : sv.y;
                    float dd;
                    if (la == sClab[cj]) dd = 1.0f - s;
                    else                 dd = fmaxf(s - MARGIN, 0.0f);
                    local += dd * dd;
                }
            }
        }
    }
    if (bi != bj) local *= 2.0f;   // symmetric tile counted twice

    // reduce: warp -> block -> global; last CTA finalizes
    for (int off = 16; off > 0; off >>= 1)
        local += __shfl_xor_sync(0xFFFFFFFF, local, off);
    float* sRed = reinterpret_cast<float*>(smem + SM_RED);
    if (lane == 0) sRed[wid] = local;
    __syncthreads();
    if (tid == 0) {
        const float t = sRed[0] + sRed[1] + sRed[2] + sRed[3];
        atomicAdd(&g_sum, (double)t);
        __threadfence();
        const unsigned int r = atomicAdd(&g_done, 1u);
        if (r == NBLOCKS - 1) {
            const double num_pairs = (double)N_ROWS * (double)(N_ROWS - 1);
            out[0] = (float)(g_sum / num_pairs);
            g_done = 0;   // reset for next replay (deterministic)
        }
    }
}

// ---------------------------------------------------------------------------
extern "C" void kernel_launch(void* const* d_in, const int* in_sizes, int n_in,
                              void* d_out, int out_size) {
    const float* embeddings = (const float*)d_in[0];
    const int*   labels     = (const int*)d_in[1];
    float*       out        = (float*)d_out;

    static bool attr_set = false;
    if (!attr_set) {
        cudaFuncSetAttribute(loss_kernel,
                             cudaFuncAttributeMaxDynamicSharedMemorySize, SM_TOT);
        attr_set = true;
    }

    normalize_kernel<<<N_ROWS / 8, 256>>>(embeddings);
    loss_kernel<<<NBLOCKS, 128, SM_TOT>>>(labels, out);
}

// round 17
// speedup vs baseline: 1.8442x; 1.0153x over previous
#include <cuda_runtime.h>
#include <cuda_fp16.h>
#include <math.h>
#include <cstdint>

#define N_ROWS 8192
#define DIM    512
#define MARGIN 0.5f

#define TILE   128
#define KC     64                      // K chunk (fp16 elems)
#define NCHUNK (DIM / KC)              // 8
#define NTILES (N_ROWS / TILE)         // 64
#define NBLOCKS (NTILES * (NTILES + 1) / 2)   // 2080

#define PITCH  (KC * 2 + 16)           // 144 B row pitch, ldmatrix conflict-free

// Scratch: normalized embeddings in fp16
__device__ __half g_Ehf[(size_t)N_ROWS * DIM];
__device__ double g_sum;
__device__ unsigned int g_done = 0;

// ---------------------------------------------------------------------------
__device__ __forceinline__ uint32_t smem_u32(const void* p) {
    uint32_t a;
    asm("{ .reg .u64 t; cvta.to.shared.u64 t, %1; cvt.u32.u64 %0, t; }"
        : "=r"(a) : "l"(p));
    return a;
}
__device__ __forceinline__ void ldmx4(uint32_t* r, uint32_t addr) {
    asm volatile("ldmatrix.sync.aligned.m8n8.x4.shared.b16 {%0,%1,%2,%3}, [%4];"
                 : "=r"(r[0]), "=r"(r[1]), "=r"(r[2]), "=r"(r[3]) : "r"(addr));
}
// f16-accumulate MMA
__device__ __forceinline__ void mma16816_f16(uint32_t* d, const uint32_t* a,
                                             uint32_t b0, uint32_t b1) {
    asm volatile(
        "mma.sync.aligned.m16n8k16.row.col.f16.f16.f16.f16 "
        "{%0,%1}, {%2,%3,%4,%5}, {%6,%7}, {%0,%1};"
        : "+r"(d[0]), "+r"(d[1])
        : "r"(a[0]), "r"(a[1]), "r"(a[2]), "r"(a[3]), "r"(b0), "r"(b1));
}
__device__ __forceinline__ void cp_async16(uint32_t smem_dst, const void* gmem_src) {
    asm volatile("cp.async.cg.shared.global [%0], [%1], 16;"
                 :: "r"(smem_dst), "l"(gmem_src) : "memory");
}
__device__ __forceinline__ void cp_commit() {
    asm volatile("cp.async.commit_group;" ::: "memory");
}
template <int N>
__device__ __forceinline__ void cp_wait() {
    asm volatile("cp.async.wait_group %0;" :: "n"(N) : "memory");
}

// ---------------------------------------------------------------------------
// Kernel 1: normalize + fp16 convert. Warp per row, 8 rows/block.
// ---------------------------------------------------------------------------
__global__ void normalize_kernel(const float* __restrict__ emb) {
    const int wid  = threadIdx.x >> 5;
    const int lane = threadIdx.x & 31;
    const int row  = blockIdx.x * 8 + wid;
    if (row == 0 && lane == 0) g_sum = 0.0;   // stream-ordered before loss_kernel

    const float4* src = reinterpret_cast<const float4*>(emb + (size_t)row * DIM);
    float4 v[4];
    float ss = 0.0f;
#pragma unroll
    for (int k = 0; k < 4; k++) {
        v[k] = src[lane + 32 * k];
        ss += v[k].x*v[k].x + v[k].y*v[k].y + v[k].z*v[k].z + v[k].w*v[k].w;
    }
    for (int off = 16; off > 0; off >>= 1)
        ss += __shfl_xor_sync(0xFFFFFFFF, ss, off);
    const float sc = 1.0f / fmaxf(sqrtf(ss), 1e-12f);

    uint2* dst = reinterpret_cast<uint2*>(g_Ehf + (size_t)row * DIM);
#pragma unroll
    for (int k = 0; k < 4; k++) {
        __half2 p0 = __floats2half2_rn(v[k].x * sc, v[k].y * sc);
        __half2 p1 = __floats2half2_rn(v[k].z * sc, v[k].w * sc);
        uint2 o;
        o.x = *reinterpret_cast<uint32_t*>(&p0);
        o.y = *reinterpret_cast<uint32_t*>(&p1);
        dst[lane + 32 * k] = o;
    }
}

// ---------------------------------------------------------------------------
// Kernel 2: fp16 (f16-acc) sim-GEMM, upper triangle, fused loss + finalize.
// 128x128 CTA tile, 4 warps (2x2), warp tile 64x64, cp.async double buffer.
// 3 CTAs/SM (12 warps/SM) for latency hiding; mainloop compiler-scheduled.
// ---------------------------------------------------------------------------
#define SM_RLAB 0
#define SM_CLAB 512
#define SM_RED  1024
#define SM_BUF  1088
#define BUFSZ   (2 * TILE * PITCH)     // A+B per stage: 36864 B
#define SM_TOT  (SM_BUF + 2 * BUFSZ)   // 74816 B; 3 CTAs = 224448 B <= 228 KB

__global__ __launch_bounds__(128, 3) void loss_kernel(const int* __restrict__ labels,
                                                      float* __restrict__ out) {
    extern __shared__ char smem[];
    const uint32_t sbase = smem_u32(smem);
    const int tid  = threadIdx.x;      // 0..127
    const int wid  = tid >> 5;         // 0..3
    const int lane = tid & 31;
    const int wr   = wid >> 1;    // 0..1 : 64-row band
    const int wc   = wid & 1;     // 0..1 : 64-col band

    // Triangular decode blockIdx.x -> (bi, bj), bj >= bi
    int idx = blockIdx.x;
    int bi = (int)((2.0f * NTILES + 1.0f
                    - sqrtf((2.0f*NTILES+1.0f)*(2.0f*NTILES+1.0f) - 8.0f*idx)) * 0.5f);
    while (bi > 0 && bi * NTILES - (bi * (bi - 1)) / 2 > idx) bi--;
    while ((bi + 1) * NTILES - ((bi + 1) * bi) / 2 <= idx) bi++;
    const int bj = bi + (idx - (bi * NTILES - (bi * (bi - 1)) / 2));

    const int rowBase = bi * TILE;
    const int colBase = bj * TILE;

    int* sRlab = reinterpret_cast<int*>(smem + SM_RLAB);
    int* sClab = reinterpret_cast<int*>(smem + SM_CLAB);
    sRlab[tid] = labels[rowBase + tid];
    sClab[tid] = labels[colBase + tid];

    // cp.async mapping: 16 x 16B per thread per chunk (2048 total)
    int cp_row[16]; int cp_isB[16]; int cp_g[16];
#pragma unroll
    for (int p = 0; p < 16; p++) {
        const int e = tid + p * 128;
        cp_isB[p] = e >> 10;
        cp_row[p] = (e & 1023) >> 3;
        cp_g[p]   = e & 7;
    }

    // ldmatrix per-lane bases (relative to buffer start)
    const int lrow = lane & 15;
    const uint32_t khalf = (lane & 16) ? 16u : 0u;
    const uint32_t aRel = (uint32_t)(wr * 64 + lrow) * PITCH + khalf;
    const uint32_t bRel = (uint32_t)(TILE * PITCH) + (uint32_t)(wc * 64 + lrow) * PITCH + khalf;

    // f16 accumulators: [mi][ni] -> 2 packed regs
    uint32_t acc[4][8][2];
#pragma unroll
    for (int i = 0; i < 4; i++)
#pragma unroll
        for (int j = 0; j < 8; j++) { acc[i][j][0] = 0u; acc[i][j][1] = 0u; }

    // ---- prefetch chunk 0 into buffer 0 ----
#pragma unroll
    for (int p = 0; p < 16; p++) {
        const int gro = (cp_isB[p] ? colBase : rowBase) + cp_row[p];
        const uint32_t dst = sbase + SM_BUF
            + (uint32_t)(cp_isB[p] * (TILE * PITCH) + cp_row[p] * PITCH + cp_g[p] * 16);
        cp_async16(dst, g_Ehf + (size_t)gro * DIM + cp_g[p] * 8);
    }
    cp_commit();

#pragma unroll 1
    for (int c = 0; c < NCHUNK; c++) {
        const uint32_t curBuf = sbase + SM_BUF + (uint32_t)((c & 1) * BUFSZ);

        if (c + 1 < NCHUNK) {
            const uint32_t nxtBuf = sbase + SM_BUF + (uint32_t)(((c + 1) & 1) * BUFSZ);
            const int koff = (c + 1) * KC;
#pragma unroll
            for (int p = 0; p < 16; p++) {
                const int gro = (cp_isB[p] ? colBase : rowBase) + cp_row[p];
                const uint32_t dst = nxtBuf
                    + (uint32_t)(cp_isB[p] * (TILE * PITCH) + cp_row[p] * PITCH + cp_g[p] * 16);
                cp_async16(dst, g_Ehf + (size_t)gro * DIM + koff + cp_g[p] * 8);
            }
            cp_commit();
            cp_wait<1>();
        } else {
            cp_wait<0>();
        }
        __syncthreads();

        const uint32_t aAddr = curBuf + aRel;
        const uint32_t bAddr = curBuf + bRel;
#pragma unroll
        for (int ks = 0; ks < KC / 16; ks++) {
            const uint32_t ko = ks * 32;  // bytes
            uint32_t a[4][4];
#pragma unroll
            for (int mi = 0; mi < 4; mi++)
                ldmx4(a[mi], aAddr + (uint32_t)(mi * 16) * PITCH + ko);
            uint32_t b[4][4];
#pragma unroll
            for (int nb = 0; nb < 4; nb++)
                ldmx4(b[nb], bAddr + (uint32_t)(nb * 16) * PITCH + ko);
#pragma unroll
            for (int mi = 0; mi < 4; mi++) {
#pragma unroll
                for (int ni = 0; ni < 8; ni++) {
                    const uint32_t b0 = b[ni >> 1][ni & 1];
                    const uint32_t b1 = b[ni >> 1][2 + (ni & 1)];
                    mma16816_f16(acc[mi][ni], a[mi], b0, b1);
                }
            }
        }
        __syncthreads();
    }

    // ---- fused loss epilogue on f16 register fragments ----
    float local = 0.0f;
#pragma unroll
    for (int mi = 0; mi < 4; mi++) {
        const int r0 = wr * 64 + mi * 16 + (lane >> 2);
#pragma unroll
        for (int ni = 0; ni < 8; ni++) {
            const int c0 = wc * 64 + ni * 8 + ((lane & 3) << 1);
#pragma unroll
            for (int h = 0; h < 2; h++) {
                const int ri = r0 + h * 8;
                const int gi = rowBase + ri;
                const int la = sRlab[ri];
                const __half2 hv = *reinterpret_cast<const __half2*>(&acc[mi][ni][h]);
                const float2 sv = __half22float2(hv);
#pragma unroll
                for (int q = 0; q < 2; q++) {
                    const int cj = c0 + q;
                    const int gj = colBase + cj;
                    if (gi == gj) continue;
                    const float s = (q == 0) ? sv.x : sv.y;
                    float dd;
                    if (la == sClab[cj]) dd = 1.0f - s;
                    else                 dd = fmaxf(s - MARGIN, 0.0f);
                    local += dd * dd;
                }
            }
        }
    }
    if (bi != bj) local *= 2.0f;   // symmetric tile counted twice

    // reduce: warp -> block -> global; last CTA finalizes
    for (int off = 16; off > 0; off >>= 1)
        local += __shfl_xor_sync(0xFFFFFFFF, local, off);
    float* sRed = reinterpret_cast<float*>(smem + SM_RED);
    if (lane == 0) sRed[wid] = local;
    __syncthreads();
    if (tid == 0) {
        const float t = sRed[0] + sRed[1] + sRed[2] + sRed[3];
        atomicAdd(&g_sum, (double)t);
        __threadfence();
        const unsigned int r = atomicAdd(&g_done, 1u);
        if (r == NBLOCKS - 1) {
            const double num_pairs = (double)N_ROWS * (double)(N_ROWS - 1);
            out[0] = (float)(g_sum / num_pairs);
            g_done = 0;   // reset for next replay (deterministic)
        }
    }
}

// ---------------------------------------------------------------------------
extern "C" void kernel_launch(void* const* d_in, const int* in_sizes, int n_in,
                              void* d_out, int out_size) {
    const float* embeddings = (const float*)d_in[0];
    const int*   labels     = (const int*)d_in[1];
    float*       out        = (float*)d_out;

    static bool attr_set = false;
    if (!attr_set) {
        cudaFuncSetAttribute(loss_kernel,
                             cudaFuncAttributeMaxDynamicSharedMemorySize, SM_TOT);
        attr_set = true;
    }

    normalize_kernel<<<N_ROWS / 8, 256>>>(embeddings);
    loss_kernel<<<NBLOCKS, 128, SM_TOT>>>(labels, out);
}